// round 17
// baseline (speedup 1.0000x reference)
#include <cuda_runtime.h>

// embedding_pooling: out[b, (c-1)*256 + d] = relu(max_{l: label[b,l]==c} x[b,l,d]), empty->0
//  - relu + empty-case == fmax chain initialized at 0.
//  - Labels are int32 on device (proven R2 fail / R3 pass).
//
// Terminal structure (R7/R12/R16, 22.5us x3, DRAM ~62% = measured system
// ceiling for this shape): 1280 CTAs x 128 thr, single resident wave,
// ballot-gather, team-strided float4 stream with 8 LDG.128 in flight, __ldcs.
// This round: minimal-latency phase 1 — int4 label load (1 LDG.128/thread),
// 4 ballots, per-warp bases derived locally; 2 syncs, no serialized scan.

#define BATCH 256
#define LSEQ  512
#define DDIM  256
#define NC    5

#define FM4(a, v)  { a.x = fmaxf(a.x, v.x); a.y = fmaxf(a.y, v.y); \
                     a.z = fmaxf(a.z, v.z); a.w = fmaxf(a.w, v.w); }

__global__ __launch_bounds__(128, 9)
void embedding_pooling_kernel(const float* __restrict__ x,
                              const int* __restrict__ labels,
                              float* __restrict__ out)
{
    __shared__ int    s_idx[LSEQ];
    __shared__ int    s_wcnt[4];
    __shared__ float4 s_red[2][64];

    const int tid  = threadIdx.x;
    const int w    = tid >> 5;
    const int lane = tid & 31;
    const int b    = blockIdx.x / NC;
    const int c    = (blockIdx.x % NC) + 1;

    // ---- Phase 1: gather l with label == c (any order — max is commutative).
    // One LDG.128 per thread covers labels 4*tid .. 4*tid+3.
    const int4 L = ((const int4*)(labels + (size_t)b * LSEQ))[tid];
    const bool f0 = (L.x == c), f1 = (L.y == c), f2 = (L.z == c), f3 = (L.w == c);
    const unsigned m0 = __ballot_sync(0xffffffffu, f0);
    const unsigned m1 = __ballot_sync(0xffffffffu, f1);
    const unsigned m2 = __ballot_sync(0xffffffffu, f2);
    const unsigned m3 = __ballot_sync(0xffffffffu, f3);
    const int p0 = __popc(m0), p1 = __popc(m1), p2 = __popc(m2), p3 = __popc(m3);
    if (lane == 0) s_wcnt[w] = p0 + p1 + p2 + p3;
    __syncthreads();
    // Each thread derives its warp's base and the total locally (4 adds).
    const int c0 = s_wcnt[0], c1 = s_wcnt[1], c2 = s_wcnt[2], c3 = s_wcnt[3];
    const int n  = c0 + c1 + c2 + c3;
    int base = 0;
    if (w > 0) base += c0;
    if (w > 1) base += c1;
    if (w > 2) base += c2;
    const unsigned below = (1u << lane) - 1u;
    // Warp-internal layout: [m0 block | m1 block | m2 block | m3 block].
    if (f0) s_idx[base + __popc(m0 & below)]                = 4 * tid + 0;
    if (f1) s_idx[base + p0 + __popc(m1 & below)]           = 4 * tid + 1;
    if (f2) s_idx[base + p0 + p1 + __popc(m2 & below)]      = 4 * tid + 2;
    if (f3) s_idx[base + p0 + p1 + p2 + __popc(m3 & below)] = 4 * tid + 3;
    __syncthreads();

    // ---- Phase 2: team-strided max (team = 64 thr owns rows j == team mod 2;
    //      thread owns one float4 column). 8 streaming LDG.128 in flight.
    const int team = tid >> 6;
    const int col  = tid & 63;
    const float4* __restrict__ Xb = (const float4*)x + (size_t)b * LSEQ * (DDIM / 4);

    float4 acc = make_float4(0.f, 0.f, 0.f, 0.f);
    int j = team;
    for (; j + 14 < n; j += 16) {
        const int l0 = s_idx[j];
        const int l1 = s_idx[j +  2];
        const int l2 = s_idx[j +  4];
        const int l3 = s_idx[j +  6];
        const int l4 = s_idx[j +  8];
        const int l5 = s_idx[j + 10];
        const int l6 = s_idx[j + 12];
        const int l7 = s_idx[j + 14];
        const float4 v0 = __ldcs(Xb + (size_t)l0 * 64 + col);
        const float4 v1 = __ldcs(Xb + (size_t)l1 * 64 + col);
        const float4 v2 = __ldcs(Xb + (size_t)l2 * 64 + col);
        const float4 v3 = __ldcs(Xb + (size_t)l3 * 64 + col);
        const float4 v4 = __ldcs(Xb + (size_t)l4 * 64 + col);
        const float4 v5 = __ldcs(Xb + (size_t)l5 * 64 + col);
        const float4 v6 = __ldcs(Xb + (size_t)l6 * 64 + col);
        const float4 v7 = __ldcs(Xb + (size_t)l7 * 64 + col);
        FM4(acc, v0); FM4(acc, v1); FM4(acc, v2); FM4(acc, v3);
        FM4(acc, v4); FM4(acc, v5); FM4(acc, v6); FM4(acc, v7);
    }
    for (; j < n; j += 2) {
        const float4 v = __ldcs(Xb + (size_t)s_idx[j] * 64 + col);
        FM4(acc, v);
    }

    s_red[team][col] = acc;
    __syncthreads();

    // ---- Phase 3: fold the 2 teams; one float4 store per column.
    if (tid < 64) {
        float4 mm = s_red[0][tid];
        const float4 v = s_red[1][tid];
        FM4(mm, v);
        float4* O4 = (float4*)out;
        O4[(size_t)b * (NC * (DDIM / 4)) + (size_t)(c - 1) * (DDIM / 4) + tid] = mm;
    }
}

extern "C" void kernel_launch(void* const* d_in, const int* in_sizes, int n_in,
                              void* d_out, int out_size)
{
    const float* x      = (const float*)d_in[0];
    const int*   labels = (const int*)d_in[1];
    float*       out    = (float*)d_out;

    embedding_pooling_kernel<<<BATCH * NC, 128>>>(x, labels, out);
}